// round 1
// baseline (speedup 1.0000x reference)
#include <cuda_runtime.h>
#include <cuda_bf16.h>

// 5x5 confusion-matrix scratch (global device array: allocation-free rule).
static __device__ unsigned int g_hist[25];

__global__ void zero_hist_kernel() {
    if (threadIdx.x < 25) g_hist[threadIdx.x] = 0u;
}

__device__ __forceinline__ int argmax5(float v0, float v1, float v2, float v3, float v4) {
    // first-max semantics (strict >) to match jnp.argmax
    int bi = 0; float bv = v0;
    if (v1 > bv) { bv = v1; bi = 1; }
    if (v2 > bv) { bv = v2; bi = 2; }
    if (v3 > bv) { bv = v3; bi = 3; }
    if (v4 > bv) { bv = v4; bi = 4; }
    return bi;
}

// Warp-aggregated shared-histogram increment: one atomic per distinct bin per warp.
__device__ __forceinline__ void agg_inc(unsigned int* sh, int bin) {
    unsigned int mask = __match_any_sync(0xffffffffu, bin);
    int leader = __ffs(mask) - 1;
    if ((int)(threadIdx.x & 31) == leader)
        atomicAdd(&sh[bin], (unsigned int)__popc(mask));
}

__global__ void __launch_bounds__(256, 8) hist_kernel(
    const float4* __restrict__ logits4,   // 5 float4 per 4-row group
    const int4*  __restrict__ targets4,
    int ngroups)
{
    __shared__ unsigned int sh[25];
    const int t = threadIdx.x;
    if (t < 25) sh[t] = 0u;
    __syncthreads();

    const int stride = gridDim.x * blockDim.x;
    for (int g = blockIdx.x * blockDim.x + t; g < ngroups; g += stride) {
        const float4* p = logits4 + (size_t)g * 5;
        float4 a = __ldg(p + 0);
        float4 b = __ldg(p + 1);
        float4 c = __ldg(p + 2);
        float4 d = __ldg(p + 3);
        float4 e = __ldg(p + 4);
        int4 tg  = __ldg(targets4 + g);

        int p0 = argmax5(a.x, a.y, a.z, a.w, b.x);
        int p1 = argmax5(b.y, b.z, b.w, c.x, c.y);
        int p2 = argmax5(c.z, c.w, d.x, d.y, d.z);
        int p3 = argmax5(d.w, e.x, e.y, e.z, e.w);

        agg_inc(sh, tg.x * 5 + p0);
        agg_inc(sh, tg.y * 5 + p1);
        agg_inc(sh, tg.z * 5 + p2);
        agg_inc(sh, tg.w * 5 + p3);
    }

    __syncthreads();
    if (t < 25) {
        unsigned int v = sh[t];
        if (v) atomicAdd(&g_hist[t], v);
    }
}

__global__ void finalize_kernel(const float* __restrict__ logits,
                                const int*  __restrict__ targets,
                                int n, int tail_start,
                                float* __restrict__ out)
{
    if (blockIdx.x == 0 && threadIdx.x == 0) {
        unsigned int h[25];
        #pragma unroll
        for (int i = 0; i < 25; i++) h[i] = g_hist[i];

        // tail rows (n % 4), scalar
        for (int r = tail_start; r < n; r++) {
            const float* L = logits + (size_t)r * 5;
            int bi = 0; float bv = L[0];
            #pragma unroll
            for (int i = 1; i < 5; i++) { float v = L[i]; if (v > bv) { bv = v; bi = i; } }
            h[targets[r] * 5 + bi] += 1u;
        }

        double row[5] = {0,0,0,0,0}, col[5] = {0,0,0,0,0};
        double tot = 0.0, num = 0.0;
        #pragma unroll
        for (int i = 0; i < 5; i++) {
            #pragma unroll
            for (int j = 0; j < 5; j++) {
                double c = (double)h[i * 5 + j];
                double w = (double)((i - j) * (i - j)) * (1.0 / 16.0);
                num += w * c;
                row[i] += c;
                col[j] += c;
                tot += c;
            }
        }
        double den = 0.0;
        #pragma unroll
        for (int i = 0; i < 5; i++) {
            #pragma unroll
            for (int j = 0; j < 5; j++) {
                double w = (double)((i - j) * (i - j)) * (1.0 / 16.0);
                den += w * (row[i] * col[j] / tot);
            }
        }
        // reference returns 1 - qwk = num / (den + 1e-6)
        out[0] = (float)(num / (den + 1e-6));
    }
}

extern "C" void kernel_launch(void* const* d_in, const int* in_sizes, int n_in,
                              void* d_out, int out_size) {
    const float* logits  = (const float*)d_in[0];
    const int*   targets = (const int*)d_in[1];
    const int n = in_sizes[1];           // number of samples (targets count)
    const int ngroups = n >> 2;          // 4 rows per group

    zero_hist_kernel<<<1, 32>>>();

    const int threads = 256;
    int blocks = (ngroups + threads - 1) / threads;
    if (blocks > 1184) blocks = 1184;    // 148 SMs x 8 blocks
    if (blocks > 0)
        hist_kernel<<<blocks, threads>>>((const float4*)logits,
                                         (const int4*)targets, ngroups);

    finalize_kernel<<<1, 32>>>(logits, targets, n, ngroups << 2, (float*)d_out);
}

// round 4
// speedup vs baseline: 1.2679x; 1.2679x over previous
#include <cuda_runtime.h>
#include <cuda_bf16.h>

// Scratch (allocation-free rule: __device__ globals, zero-init at load).
// g_acc[0..4]=pred hist, [5..9]=target hist, [10]=sum (t-p)^2.
// Invariant: g_acc == 0 at entry to kernel_launch (finalize resets it).
static __device__ unsigned int g_acc[11];

__device__ __forceinline__ int argmax5(float v0, float v1, float v2, float v3, float v4) {
    // first-max semantics (strict >) to match jnp.argmax
    int bi = 0; float bv = v0;
    if (v1 > bv) { bv = v1; bi = 1; }
    if (v2 > bv) { bv = v2; bi = 2; }
    if (v3 > bv) { bv = v3; bi = 3; }
    if (v4 > bv) { bv = v4; bi = 4; }
    return bi;
}

__global__ void __launch_bounds__(256, 4) qwk_main(
    const float4* __restrict__ logits4,   // 5 float4 per 4-row group
    const int4*  __restrict__ targets4,
    const float* __restrict__ logits,     // tail rows
    const int*  __restrict__ targets,
    int n, int ngroups)
{
    __shared__ unsigned int sh[11];
    const int t = threadIdx.x;
    if (t < 11) sh[t] = 0u;
    __syncthreads();

    // Register accumulators: two packed 5x12-bit hists + d^2 sum.
    // Max rows/thread ~56 << 4095 lane cap.
    unsigned long long pred_pack = 0ull;
    unsigned long long tgt_pack  = 0ull;
    unsigned int d2 = 0u;

    // Tail rows (n % 4) — dead at runtime when 4 | n.
    if (blockIdx.x == 0 && t == 0) {
        for (int r = ngroups << 2; r < n; r++) {
            const float* L = logits + (size_t)r * 5;
            int p = argmax5(L[0], L[1], L[2], L[3], L[4]);
            int tv = targets[r];
            pred_pack += 1ull << (12 * p);
            tgt_pack  += 1ull << (12 * tv);
            int d = tv - p;
            d2 += (unsigned int)(d * d);
        }
    }

    const int stride = gridDim.x * blockDim.x;
    for (int g = blockIdx.x * blockDim.x + t; g < ngroups; g += stride) {
        const float4* ptr = logits4 + (size_t)g * 5;
        float4 a = __ldg(ptr + 0);
        float4 b = __ldg(ptr + 1);
        float4 c = __ldg(ptr + 2);
        float4 d = __ldg(ptr + 3);
        float4 e = __ldg(ptr + 4);
        int4 tg  = __ldg(targets4 + g);

        int p0 = argmax5(a.x, a.y, a.z, a.w, b.x);
        int p1 = argmax5(b.y, b.z, b.w, c.x, c.y);
        int p2 = argmax5(c.z, c.w, d.x, d.y, d.z);
        int p3 = argmax5(d.w, e.x, e.y, e.z, e.w);

        pred_pack += (1ull << (12 * p0)) + (1ull << (12 * p1))
                   + (1ull << (12 * p2)) + (1ull << (12 * p3));
        tgt_pack  += (1ull << (12 * tg.x)) + (1ull << (12 * tg.y))
                   + (1ull << (12 * tg.z)) + (1ull << (12 * tg.w));
        int e0 = tg.x - p0, e1 = tg.y - p1, e2 = tg.z - p2, e3 = tg.w - p3;
        d2 += (unsigned int)(e0*e0 + e1*e1 + e2*e2 + e3*e3);
    }

    // Unpack 12-bit lanes -> 11 u32, warp-reduce, one shared atomic per warp,
    // then one global atomic per counter per block.
    unsigned int v[11];
    #pragma unroll
    for (int i = 0; i < 5; i++) {
        v[i]     = (unsigned int)((pred_pack >> (12 * i)) & 0xFFFull);
        v[5 + i] = (unsigned int)((tgt_pack  >> (12 * i)) & 0xFFFull);
    }
    v[10] = d2;
    #pragma unroll
    for (int i = 0; i < 11; i++) {
        unsigned int r = __reduce_add_sync(0xffffffffu, v[i]);
        if ((t & 31) == 0 && r) atomicAdd(&sh[i], r);
    }
    __syncthreads();
    if (t < 11) {
        unsigned int r = sh[t];
        if (r) atomicAdd(&g_acc[t], r);
    }
}

__global__ void qwk_finalize(int n, float* __restrict__ out) {
    if (threadIdx.x == 0) {
        double pred_h[5], tgt_h[5];
        #pragma unroll
        for (int i = 0; i < 5; i++) {
            pred_h[i] = (double)g_acc[i];
            tgt_h[i]  = (double)g_acc[5 + i];
        }
        double num = (double)g_acc[10] * (1.0 / 16.0);
        double tot = (double)n;
        double den = 0.0;
        #pragma unroll
        for (int i = 0; i < 5; i++) {
            #pragma unroll
            for (int j = 0; j < 5; j++) {
                double w = (double)((i - j) * (i - j)) * (1.0 / 16.0);
                den += w * (tgt_h[i] * pred_h[j] / tot);
            }
        }
        // reference returns 1 - qwk = num / (den + 1e-6)
        out[0] = (float)(num / (den + 1e-6));
        // restore invariant for next call/replay
        #pragma unroll
        for (int i = 0; i < 11; i++) g_acc[i] = 0u;
    }
}

extern "C" void kernel_launch(void* const* d_in, const int* in_sizes, int n_in,
                              void* d_out, int out_size) {
    const float* logits  = (const float*)d_in[0];
    const int*   targets = (const int*)d_in[1];
    const int n = in_sizes[1];
    const int ngroups = n >> 2;

    const int threads = 256;
    int blocks = (ngroups + threads - 1) / threads;
    if (blocks < 1) blocks = 1;
    if (blocks > 592) blocks = 592;   // 148 SMs x 4 blocks: one balanced wave
    qwk_main<<<blocks, threads>>>((const float4*)logits, (const int4*)targets,
                                  logits, targets, n, ngroups);
    qwk_finalize<<<1, 32>>>(n, (float*)d_out);
}

// round 6
// speedup vs baseline: 1.2778x; 1.0078x over previous
#include <cuda_runtime.h>
#include <cuda_bf16.h>

// Scratch (allocation-free rule: __device__ globals, zero-init at load).
// g_acc[0..4]=pred hist, [5..9]=target hist, [10]=sum (t-p)^2.
// Invariant: g_acc == 0 at entry to kernel_launch (finalize resets it).
static __device__ unsigned int g_acc[11];

__device__ __forceinline__ int argmax5(float v0, float v1, float v2, float v3, float v4) {
    // first-max semantics (strict >) to match jnp.argmax
    int bi = 0; float bv = v0;
    if (v1 > bv) { bv = v1; bi = 1; }
    if (v2 > bv) { bv = v2; bi = 2; }
    if (v3 > bv) { bv = v3; bi = 3; }
    if (v4 > bv) { bv = v4; bi = 4; }
    return bi;
}

__global__ void __launch_bounds__(256, 4) qwk_main(
    const float4* __restrict__ logits4,   // 5 float4 per 4-row group
    const int4*  __restrict__ targets4,
    const float* __restrict__ logits,     // tail rows
    const int*  __restrict__ targets,
    int n, int ngroups)
{
    __shared__ unsigned int sh[11];
    const int t = threadIdx.x;
    if (t < 11) sh[t] = 0u;
    __syncthreads();

    // Register accumulators: two packed 5x12-bit hists + d^2 sum.
    // Max rows/thread ~56 << 4095 lane cap.
    unsigned long long pred_pack = 0ull;
    unsigned long long tgt_pack  = 0ull;
    unsigned int d2 = 0u;

    // Tail rows (n % 4) — dead at runtime when 4 | n.
    if (blockIdx.x == 0 && t == 0) {
        for (int r = ngroups << 2; r < n; r++) {
            const float* L = logits + (size_t)r * 5;
            int p = argmax5(L[0], L[1], L[2], L[3], L[4]);
            int tv = targets[r];
            pred_pack += 1ull << (12 * p);
            tgt_pack  += 1ull << (12 * tv);
            int d = tv - p;
            d2 += (unsigned int)(d * d);
        }
    }

    const int stride = gridDim.x * blockDim.x;
    for (int g = blockIdx.x * blockDim.x + t; g < ngroups; g += stride) {
        const float4* ptr = logits4 + (size_t)g * 5;
        float4 a = __ldg(ptr + 0);
        float4 b = __ldg(ptr + 1);
        float4 c = __ldg(ptr + 2);
        float4 d = __ldg(ptr + 3);
        float4 e = __ldg(ptr + 4);
        int4 tg  = __ldg(targets4 + g);

        int p0 = argmax5(a.x, a.y, a.z, a.w, b.x);
        int p1 = argmax5(b.y, b.z, b.w, c.x, c.y);
        int p2 = argmax5(c.z, c.w, d.x, d.y, d.z);
        int p3 = argmax5(d.w, e.x, e.y, e.z, e.w);

        pred_pack += (1ull << (12 * p0)) + (1ull << (12 * p1))
                   + (1ull << (12 * p2)) + (1ull << (12 * p3));
        tgt_pack  += (1ull << (12 * tg.x)) + (1ull << (12 * tg.y))
                   + (1ull << (12 * tg.z)) + (1ull << (12 * tg.w));
        int e0 = tg.x - p0, e1 = tg.y - p1, e2 = tg.z - p2, e3 = tg.w - p3;
        d2 += (unsigned int)(e0*e0 + e1*e1 + e2*e2 + e3*e3);
    }

    // Unpack 12-bit lanes -> 11 u32, warp-reduce, one shared atomic per warp,
    // then one global atomic per counter per block.
    unsigned int v[11];
    #pragma unroll
    for (int i = 0; i < 5; i++) {
        v[i]     = (unsigned int)((pred_pack >> (12 * i)) & 0xFFFull);
        v[5 + i] = (unsigned int)((tgt_pack  >> (12 * i)) & 0xFFFull);
    }
    v[10] = d2;
    #pragma unroll
    for (int i = 0; i < 11; i++) {
        unsigned int r = __reduce_add_sync(0xffffffffu, v[i]);
        if ((t & 31) == 0 && r) atomicAdd(&sh[i], r);
    }
    __syncthreads();
    if (t < 11) {
        unsigned int r = sh[t];
        if (r) atomicAdd(&g_acc[t], r);
    }
}

__global__ void qwk_finalize(int n, float* __restrict__ out) {
    if (threadIdx.x == 0) {
        double pred_h[5], tgt_h[5];
        #pragma unroll
        for (int i = 0; i < 5; i++) {
            pred_h[i] = (double)g_acc[i];
            tgt_h[i]  = (double)g_acc[5 + i];
        }
        double num = (double)g_acc[10] * (1.0 / 16.0);
        double inv_tot = 1.0 / (double)n;      // the ONLY FP64 divide (was 25 DDIVs)
        double den_s = 0.0;
        #pragma unroll
        for (int i = 0; i < 5; i++) {
            #pragma unroll
            for (int j = 0; j < 5; j++) {
                double w = (double)((i - j) * (i - j));
                den_s += w * (tgt_h[i] * pred_h[j]);   // pure DFMA chain
            }
        }
        double den = den_s * (1.0 / 16.0) * inv_tot;
        // reference returns 1 - qwk = num / (den + 1e-6)
        out[0] = (float)(num / (den + 1e-6));
        // restore invariant for next call/replay
        #pragma unroll
        for (int i = 0; i < 11; i++) g_acc[i] = 0u;
    }
}

extern "C" void kernel_launch(void* const* d_in, const int* in_sizes, int n_in,
                              void* d_out, int out_size) {
    const float* logits  = (const float*)d_in[0];
    const int*   targets = (const int*)d_in[1];
    const int n = in_sizes[1];
    const int ngroups = n >> 2;

    const int threads = 256;
    int blocks = (ngroups + threads - 1) / threads;
    if (blocks < 1) blocks = 1;
    if (blocks > 592) blocks = 592;   // 148 SMs x 4 blocks: one balanced wave
    qwk_main<<<blocks, threads>>>((const float4*)logits, (const int4*)targets,
                                  logits, targets, n, ngroups);
    qwk_finalize<<<1, 32>>>(n, (float*)d_out);
}